// round 6
// baseline (speedup 1.0000x reference)
#include <cuda_runtime.h>
#include <math.h>

#define BB 8
#define GG 16
#define PP 64
#define IMH 640
#define IMW 640
#define SZ 32
#define NBLOCKS (BB*PP)

__device__ double d_total = 0.0;
__device__ double d_cnt   = 0.0;
__device__ unsigned int d_done = 0;

// Per-axis bilinear sampling coords, same arithmetic order as reference
__device__ __forceinline__ void axis_coord(float origin, float len, int maxdim, int i,
                                           int& lo, int& hi, float& wq) {
    float lm = fmaxf(len - 1.0f, 0.0f);
    float s  = fminf(fmaxf(((float)i + 0.5f) * (len / (float)SZ) - 0.5f, 0.0f), lm);
    float sf = floorf(s);
    wq = s - sf;
    float vlo = sf + origin;
    float vhi = fminf(sf + 1.0f, lm) + origin;
    lo = (int)fminf(fmaxf(vlo, 0.0f), (float)(maxdim - 1));
    hi = (int)fminf(fmaxf(vhi, 0.0f), (float)(maxdim - 1));
}

__global__ void __launch_bounds__(128, 4)
fused_kernel(const float* __restrict__ gt,
             const float* __restrict__ pr,
             const float* __restrict__ imgs,
             float* __restrict__ out) {
    const unsigned FULL = 0xffffffffu;
    int t = threadIdx.x;
    int lane = t & 31;
    int warp = t >> 5;          // 0..3
    int b = blockIdx.x >> 6;
    int p = blockIdx.x & 63;

    __shared__ int   s_list[GG];
    __shared__ int   s_nm;
    __shared__ float sred[4];
    __shared__ bool  s_last;

    // Gaussian weights in registers (symmetric): W[k] for |d|=k
    float e1  = expf(-1.0f/4.5f);
    float e4  = expf(-4.0f/4.5f);
    float e9  = expf(-9.0f/4.5f);
    float e16 = expf(-16.0f/4.5f);
    float e25 = expf(-25.0f/4.5f);
    float ssum = 1.0f + 2.0f*(e1 + e4 + e9 + e16 + e25);
    float W[6];
    W[0] = 1.0f/ssum; W[1] = e1/ssum; W[2] = e4/ssum;
    W[3] = e9/ssum;   W[4] = e16/ssum; W[5] = e25/ssum;

    if (t == 0) s_nm = 0;
    __syncthreads();

    // IoU mask of this pred against all 16 gts
    const float* pb = pr + (size_t)(b*PP + p)*4;
    float px_ = pb[0], py_ = pb[1], pw_ = pb[2], ph_ = pb[3];
    if (t < GG) {
        const float* gb = gt + (size_t)(b*GG + t)*4;
        float gx = gb[0], gy = gb[1], gw_ = gb[2], gh_ = gb[3];
        float tlx = fmaxf(gx - gw_*0.5f, px_ - pw_*0.5f);
        float tly = fmaxf(gy - gh_*0.5f, py_ - ph_*0.5f);
        float brx = fminf(gx + gw_*0.5f, px_ + pw_*0.5f);
        float bry = fminf(gy + gh_*0.5f, py_ + ph_*0.5f);
        float en  = ((tlx < brx) && (tly < bry)) ? 1.0f : 0.0f;
        float ai  = (brx - tlx) * (bry - tly) * en;
        float iou = ai / (gw_*gh_ + pw_*ph_ - ai + 1e-16f);
        if ((iou > 0.3f) && (pw_ > 2.0f) && (ph_ > 2.0f)) {
            int i = atomicAdd(&s_nm, 1);
            s_list[i] = t;
        }
    }
    __syncthreads();
    int nm = s_nm;

    float accf = 0.0f;
    if (nm > 0) {
        const float C1 = 6.5025f;    // (0.01*255)^2
        const float C2 = 58.5225f;   // (0.03*255)^2
        const float* imb = imgs + (size_t)b * 3 * IMH * IMW;

        // pred coords: lane as column (x-axis) and lane as row (y-axis)
        float x0p = floorf(px_), y0p = floorf(py_);
        float wp  = floorf(px_ + pw_) - x0p;
        float hp  = floorf(py_ + ph_) - y0p;
        int pxlo, pxhi; float pwx;
        int pylo, pyhi; float pwy;
        axis_coord(x0p, wp, IMW, lane, pxlo, pxhi, pwx);
        axis_coord(y0p, hp, IMH, lane, pylo, pyhi, pwy);

        // warps stride over (gt, channel) work items
        for (int q = warp; q < 3*nm; q += 4) {
            int mi = q / 3;
            int c  = q - mi*3;
            int g  = s_list[mi];
            const float* imc = imb + (size_t)c * IMH * IMW;

            const float* gb = gt + (size_t)(b*GG + g)*4;
            float gx = gb[0], gy = gb[1], gwd = gb[2], ghd = gb[3];
            float x0g = floorf(gx), y0g = floorf(gy);
            float wg  = floorf(gx + gwd) - x0g;
            float hg  = floorf(gy + ghd) - y0g;
            int gxlo, gxhi; float gwx;
            int gylo, gyhi; float gwy;
            axis_coord(x0g, wg, IMW, lane, gxlo, gxhi, gwx);
            axis_coord(y0g, hg, IMH, lane, gylo, gyhi, gwy);

            // register ring buffer: last 11 rows of the 4 H-conv fields
            float h0r[11], h1r[11], h2r[11], h3r[11];

            for (int rb = 0; rb < 44; rb += 11) {
                #pragma unroll
                for (int i = 0; i < 11; i++) {
                    int r = rb + i;               // streamed row
                    if (r < SZ) {
                        // row-r sampling coords live in lane r's registers
                        int   pyl  = __shfl_sync(FULL, pylo, r);
                        int   pyh  = __shfl_sync(FULL, pyhi, r);
                        float pwyr = __shfl_sync(FULL, pwy,  r);
                        int   gyl  = __shfl_sync(FULL, gylo, r);
                        int   gyh  = __shfl_sync(FULL, gyhi, r);
                        float gwyr = __shfl_sync(FULL, gwy,  r);

                        // crop pred pixel (x) and gt pixel (y) at (r, lane)
                        float xv, yv;
                        {
                            int blo = pyl*IMW, bhi = pyh*IMW;
                            float tl = __ldg(imc + blo + pxlo);
                            float tr = __ldg(imc + blo + pxhi);
                            float bl = __ldg(imc + bhi + pxlo);
                            float br = __ldg(imc + bhi + pxhi);
                            float top = tl*(1.0f-pwx) + tr*pwx;
                            float bot = bl*(1.0f-pwx) + br*pwx;
                            xv = top*(1.0f-pwyr) + bot*pwyr;
                        }
                        {
                            int blo = gyl*IMW, bhi = gyh*IMW;
                            float tl = __ldg(imc + blo + gxlo);
                            float tr = __ldg(imc + blo + gxhi);
                            float bl = __ldg(imc + bhi + gxlo);
                            float br = __ldg(imc + bhi + gxhi);
                            float top = tl*(1.0f-gwx) + tr*gwx;
                            float bot = bl*(1.0f-gwx) + br*gwx;
                            yv = top*(1.0f-gwyr) + bot*gwyr;
                        }

                        // L1 term (covers every pixel exactly once)
                        accf += fabsf(xv*(1.0f/255.0f) - yv*(1.0f/255.0f));

                        // horizontal 11-tap conv via shuffles, zero-pad SAME
                        float h0=0.f, h1=0.f, h2=0.f, h3=0.f;
                        #pragma unroll
                        for (int d = -5; d <= 5; d++) {
                            float xs = __shfl_sync(FULL, xv, lane + d);
                            float ys = __shfl_sync(FULL, yv, lane + d);
                            if ((unsigned)(lane + d) < 32u) {
                                float wv = W[d < 0 ? -d : d];
                                h0 += wv * xs;
                                h1 += wv * ys;
                                h2 += wv * (xs*xs + ys*ys);
                                h3 += wv * (xs*ys);
                            }
                        }
                        h0r[i]=h0; h1r[i]=h1; h2r[i]=h2; h3r[i]=h3;
                    }

                    // output row o = r-5: its full V window is now in the ring
                    int o = r - 5;
                    if (o >= 0 && o < SZ) {
                        float v0=0.f, v1=0.f, v2=0.f, v3=0.f;
                        #pragma unroll
                        for (int d = -5; d <= 5; d++) {
                            int row = o + d;
                            if ((unsigned)row < (unsigned)SZ) {
                                int slot = (i + d + 6) % 11;   // (o+d) mod 11, static
                                float wv = W[d < 0 ? -d : d];
                                v0 += wv * h0r[slot];
                                v1 += wv * h1r[slot];
                                v2 += wv * h2r[slot];
                                v3 += wv * h3r[slot];
                            }
                        }
                        float mu1 = v0, mu2 = v1;
                        float mu1sq = mu1*mu1, mu2sq = mu2*mu2, mu12 = mu1*mu2;
                        float sS  = v2 - mu1sq - mu2sq;   // s1 + s2
                        float s12 = v3 - mu12;
                        float ssim = ((2.0f*mu12 + C1) * (2.0f*s12 + C2))
                                   / ((mu1sq + mu2sq + C1) * (sS + C2));
                        accf += 1.0f - ssim;
                    }
                }
            }
        }
    }

    // block reduction (4 warps)
    #pragma unroll
    for (int o = 16; o > 0; o >>= 1) accf += __shfl_down_sync(FULL, accf, o);
    if (lane == 0) sred[warp] = accf;
    __syncthreads();
    if (t == 0) {
        float v = sred[0] + sred[1] + sred[2] + sred[3];
        if (nm > 0) {
            atomicAdd(&d_total, (double)v);
            atomicAdd(&d_cnt, (double)nm);
        }
    }

    // completion counter: last block finalizes and resets accumulators
    __threadfence();
    if (t == 0) {
        unsigned prev = atomicAdd(&d_done, 1u);
        s_last = (prev == (unsigned)(NBLOCKS - 1));
    }
    __syncthreads();
    if (s_last && t == 0) {
        double cnt = d_cnt * (double)(3*SZ*SZ);
        out[0] = (cnt > 0.0) ? (float)(d_total / fmax(cnt, 1.0)) : 0.0f;
        d_total = 0.0;
        d_cnt   = 0.0;
        d_done  = 0u;
    }
}

extern "C" void kernel_launch(void* const* d_in, const int* in_sizes, int n_in,
                              void* d_out, int out_size) {
    const float* gt   = (const float*)d_in[0];
    const float* pr   = (const float*)d_in[1];
    const float* imgs = (const float*)d_in[2];
    float* out = (float*)d_out;

    fused_kernel<<<NBLOCKS, 128>>>(gt, pr, imgs, out);
}

// round 7
// speedup vs baseline: 1.7641x; 1.7641x over previous
#include <cuda_runtime.h>
#include <math.h>

#define BB 8
#define GG 16
#define PP 64
#define IMH 640
#define IMW 640
#define SZ 32
#define NBLOCKS (BB*PP*3)

// Gaussian window weights for WIN=11, sigma=1.5 (exp(-d^2/4.5), normalized),
// accurate to ~1e-8 vs the float64 reference computation, stored as f32.
__device__ __constant__ const float GW[6] = {
    0.26601172f,   // |d|=0
    0.21300554f,   // |d|=1
    0.10936070f,   // |d|=2
    0.03600077f,   // |d|=3
    0.00759876f,   // |d|=4
    0.00102838f    // |d|=5
};

__device__ double d_total = 0.0;
__device__ double d_cnt   = 0.0;
__device__ unsigned int d_done = 0;

// Per-axis bilinear sampling coords, same arithmetic order as reference
__device__ __forceinline__ void axis_coord(float origin, float len, int maxdim, int i,
                                           int& lo, int& hi, float& wq) {
    float lm = fmaxf(len - 1.0f, 0.0f);
    float s  = fminf(fmaxf(((float)i + 0.5f) * (len / (float)SZ) - 0.5f, 0.0f), lm);
    float sf = floorf(s);
    wq = s - sf;
    float vlo = sf + origin;
    float vhi = fminf(sf + 1.0f, lm) + origin;
    lo = (int)fminf(fmaxf(vlo, 0.0f), (float)(maxdim - 1));
    hi = (int)fminf(fmaxf(vhi, 0.0f), (float)(maxdim - 1));
}

struct CropCtx {
    int   o[8];            // tl0,tr0,bl0,br0, tl1,tr1,bl1,br1
    float wx, wy0, wy1;
};

__device__ __forceinline__ void make_ctx(const float* __restrict__ box,
                                         int lane, int r0, CropCtx& cx) {
    float bx = box[0], by = box[1], bw = box[2], bh = box[3];
    float x0 = floorf(bx), y0 = floorf(by);
    float w  = floorf(bx + bw) - x0;
    float h  = floorf(by + bh) - y0;
    int xlo, xhi, ylo0, yhi0, ylo1, yhi1;
    axis_coord(x0, w, IMW, lane, xlo, xhi, cx.wx);
    axis_coord(y0, h, IMH, r0,   ylo0, yhi0, cx.wy0);
    axis_coord(y0, h, IMH, r0+1, ylo1, yhi1, cx.wy1);
    cx.o[0] = ylo0*IMW + xlo;  cx.o[1] = ylo0*IMW + xhi;
    cx.o[2] = yhi0*IMW + xlo;  cx.o[3] = yhi0*IMW + xhi;
    cx.o[4] = ylo1*IMW + xlo;  cx.o[5] = ylo1*IMW + xhi;
    cx.o[6] = yhi1*IMW + xlo;  cx.o[7] = yhi1*IMW + xhi;
}

__device__ __forceinline__ float crop2(const float* __restrict__ imc,
                                       const int* o, float wx, float wy) {
    float tl = __ldg(imc + o[0]);
    float tr = __ldg(imc + o[1]);
    float bl = __ldg(imc + o[2]);
    float br = __ldg(imc + o[3]);
    float top = tl*(1.0f-wx) + tr*wx;
    float bot = bl*(1.0f-wx) + br*wx;
    return top*(1.0f-wy) + bot*wy;
}

// Padded H-field buffers: rows -5..36 (42 rows), index = (realrow+5)*32+lane.
// Pad rows are zero and never rewritten -> V-pass needs no row guards.
#define HROWS 42

__global__ void __launch_bounds__(512, 3)
fused_kernel(const float* __restrict__ gt,
             const float* __restrict__ pr,
             const float* __restrict__ imgs,
             float* __restrict__ out) {
    const unsigned FULL = 0xffffffffu;
    int t = threadIdx.x;
    int lane = t & 31;
    int warp = t >> 5;          // 0..15
    int r0 = warp * 2;          // warp owns rows r0, r0+1; lane owns col=lane
    int idx = blockIdx.x;
    int c  = idx % 3;
    int pi = idx / 3;
    int b  = pi >> 6;
    int p  = pi & 63;

    __shared__ int    s_list[GG];
    __shared__ int    s_nm;
    __shared__ float2 Hb01[2][HROWS*SZ];   // (h0,h1) double-buffered, 21 KB
    __shared__ float2 Hb23[2][HROWS*SZ];   // (h2,h3) double-buffered, 21 KB
    __shared__ float  sred[16];
    __shared__ bool   s_last;

    if (t == 0) s_nm = 0;
    // zero the pad rows (rows -5..-1 and 32..36) of both buffers, once
    if (t < 320) {
        int prow = t >> 5;                       // 0..9
        int row  = (prow < 5) ? prow : prow + 32;
        int k = row * SZ + (t & 31);
        float2 z = make_float2(0.0f, 0.0f);
        Hb01[0][k] = z; Hb01[1][k] = z;
        Hb23[0][k] = z; Hb23[1][k] = z;
    }
    __syncthreads();

    // IoU mask of this pred against all 16 gts
    const float* pb = pr + (size_t)(b*PP + p)*4;
    float px_ = pb[0], py_ = pb[1], pw_ = pb[2], ph_ = pb[3];
    if (t < GG) {
        const float* gb = gt + (size_t)(b*GG + t)*4;
        float gx = gb[0], gy = gb[1], gw_ = gb[2], gh_ = gb[3];
        float tlx = fmaxf(gx - gw_*0.5f, px_ - pw_*0.5f);
        float tly = fmaxf(gy - gh_*0.5f, py_ - ph_*0.5f);
        float brx = fminf(gx + gw_*0.5f, px_ + pw_*0.5f);
        float bry = fminf(gy + gh_*0.5f, py_ + ph_*0.5f);
        float en  = ((tlx < brx) && (tly < bry)) ? 1.0f : 0.0f;
        float ai  = (brx - tlx) * (bry - tly) * en;
        float iou = ai / (gw_*gh_ + pw_*ph_ - ai + 1e-16f);
        if ((iou > 0.3f) && (pw_ > 2.0f) && (ph_ > 2.0f)) {
            int i = atomicAdd(&s_nm, 1);
            s_list[i] = t;
        }
    }
    __syncthreads();
    int nm = s_nm;

    if (nm > 0) {
        const float* imc = imgs + ((size_t)b * 3 + c) * IMH * IMW;
        const float C1 = 6.5025f;    // (0.01*255)^2
        const float C2 = 58.5225f;   // (0.03*255)^2
        float accf = 0.0f;

        // pred crop: channel fixed per block -> hoist out of gt loop
        CropCtx pc;
        make_ctx(pb, lane, r0, pc);
        float x0v = crop2(imc, pc.o,     pc.wx, pc.wy0);
        float x1v = crop2(imc, pc.o + 4, pc.wx, pc.wy1);

        for (int m = 0; m < nm; m++) {
            int buf = m & 1;
            CropCtx gc;
            make_ctx(gt + (size_t)(b*GG + s_list[m])*4, lane, r0, gc);
            float y0v = crop2(imc, gc.o,     gc.wx, gc.wy0);
            float y1v = crop2(imc, gc.o + 4, gc.wx, gc.wy1);

            // horizontal pass via warp shuffles, zero-pad SAME, 4 fields
            #pragma unroll
            for (int rr = 0; rr < 2; rr++) {
                float xv = rr ? x1v : x0v;
                float yv = rr ? y1v : y0v;
                float h0=0.f,h1=0.f,h2=0.f,h3=0.f;
                #pragma unroll
                for (int d = -5; d <= 5; d++) {
                    float xs = __shfl_sync(FULL, xv, lane + d);
                    float ys = __shfl_sync(FULL, yv, lane + d);
                    if ((unsigned)(lane + d) < 32u) {
                        const float wv = GW[d < 0 ? -d : d];   // immediate
                        h0 = fmaf(wv, xs, h0);
                        h1 = fmaf(wv, ys, h1);
                        h2 = fmaf(wv, fmaf(xs, xs, ys*ys), h2);
                        h3 = fmaf(wv, xs*ys, h3);
                    }
                }
                int k = (r0 + rr + 5) * SZ + lane;   // padded row index
                Hb01[buf][k] = make_float2(h0, h1);
                Hb23[buf][k] = make_float2(h2, h3);
            }
            __syncthreads();   // single barrier per gt (double buffer)

            // vertical pass over padded rows r0..r0+11, no guards (pads are zero)
            float v00=0.f,v01=0.f,v02=0.f,v03=0.f;
            float v10=0.f,v11=0.f,v12=0.f,v13=0.f;
            #pragma unroll
            for (int dd = 0; dd <= 11; dd++) {
                int k = (r0 + dd) * SZ + lane;
                float2 f01 = Hb01[buf][k];
                float2 f23 = Hb23[buf][k];
                if (dd <= 10) {                    // tap for output row r0
                    const float wv = GW[dd < 5 ? 5 - dd : dd - 5];
                    v00 = fmaf(wv, f01.x, v00);
                    v01 = fmaf(wv, f01.y, v01);
                    v02 = fmaf(wv, f23.x, v02);
                    v03 = fmaf(wv, f23.y, v03);
                }
                if (dd >= 1) {                     // tap for output row r0+1
                    const float wv = GW[dd < 6 ? 6 - dd : dd - 6];
                    v10 = fmaf(wv, f01.x, v10);
                    v11 = fmaf(wv, f01.y, v11);
                    v12 = fmaf(wv, f23.x, v12);
                    v13 = fmaf(wv, f23.y, v13);
                }
            }

            // SSIM + L1 for the two pixels
            {
                float mu1 = v00, mu2 = v01;
                float mu1sq = mu1*mu1, mu2sq = mu2*mu2, mu12 = mu1*mu2;
                float sS  = v02 - mu1sq - mu2sq;   // s1 + s2
                float s12 = v03 - mu12;
                float ssim = ((2.0f*mu12 + C1) * (2.0f*s12 + C2))
                           / ((mu1sq + mu2sq + C1) * (sS + C2));
                accf += fabsf(x0v*(1.0f/255.0f) - y0v*(1.0f/255.0f)) + (1.0f - ssim);
            }
            {
                float mu1 = v10, mu2 = v11;
                float mu1sq = mu1*mu1, mu2sq = mu2*mu2, mu12 = mu1*mu2;
                float sS  = v12 - mu1sq - mu2sq;
                float s12 = v13 - mu12;
                float ssim = ((2.0f*mu12 + C1) * (2.0f*s12 + C2))
                           / ((mu1sq + mu2sq + C1) * (sS + C2));
                accf += fabsf(x1v*(1.0f/255.0f) - y1v*(1.0f/255.0f)) + (1.0f - ssim);
            }
            // no trailing barrier: next gt writes the other buffer
        }

        // block reduction (16 warps)
        #pragma unroll
        for (int o = 16; o > 0; o >>= 1) accf += __shfl_down_sync(FULL, accf, o);
        if (lane == 0) sred[warp] = accf;
        __syncthreads();
        if (t < 16) {
            float v = sred[t];
            #pragma unroll
            for (int o = 8; o > 0; o >>= 1) v += __shfl_down_sync(0xffffu, v, o);
            if (t == 0) {
                atomicAdd(&d_total, (double)v);
                if (c == 0) atomicAdd(&d_cnt, (double)nm);
            }
        }
    }

    // completion counter: last block finalizes and resets accumulators
    __threadfence();
    if (t == 0) {
        unsigned prev = atomicAdd(&d_done, 1u);
        s_last = (prev == (unsigned)(NBLOCKS - 1));
    }
    __syncthreads();
    if (s_last && t == 0) {
        double cnt = d_cnt * (double)(3*SZ*SZ);
        out[0] = (cnt > 0.0) ? (float)(d_total / fmax(cnt, 1.0)) : 0.0f;
        d_total = 0.0;
        d_cnt   = 0.0;
        d_done  = 0u;
    }
}

extern "C" void kernel_launch(void* const* d_in, const int* in_sizes, int n_in,
                              void* d_out, int out_size) {
    const float* gt   = (const float*)d_in[0];
    const float* pr   = (const float*)d_in[1];
    const float* imgs = (const float*)d_in[2];
    float* out = (float*)d_out;

    fused_kernel<<<NBLOCKS, 512>>>(gt, pr, imgs, out);
}

// round 8
// speedup vs baseline: 1.7934x; 1.0166x over previous
#include <cuda_runtime.h>
#include <math.h>

#define BB 8
#define GG 16
#define PP 64
#define IMH 640
#define IMW 640
#define SZ 32
#define NBLOCKS (BB*PP*3)

// Gaussian window weights for WIN=11, sigma=1.5 (exp(-d^2/4.5), normalized),
// accurate to ~1e-8 vs the float64 reference; constexpr -> FFMA immediates.
__device__ constexpr float GW[6] = {
    0.26601172f,   // |d|=0
    0.21300554f,   // |d|=1
    0.10936070f,   // |d|=2
    0.03600077f,   // |d|=3
    0.00759876f,   // |d|=4
    0.00102838f    // |d|=5
};

__device__ double d_total = 0.0;
__device__ double d_cnt   = 0.0;
__device__ unsigned int d_done = 0;

// Per-axis bilinear sampling coords, same arithmetic order as reference
__device__ __forceinline__ void axis_coord(float origin, float len, int maxdim, int i,
                                           int& lo, int& hi, float& wq) {
    float lm = fmaxf(len - 1.0f, 0.0f);
    float s  = fminf(fmaxf(((float)i + 0.5f) * (len / (float)SZ) - 0.5f, 0.0f), lm);
    float sf = floorf(s);
    wq = s - sf;
    float vlo = sf + origin;
    float vhi = fminf(sf + 1.0f, lm) + origin;
    lo = (int)fminf(fmaxf(vlo, 0.0f), (float)(maxdim - 1));
    hi = (int)fminf(fmaxf(vhi, 0.0f), (float)(maxdim - 1));
}

// Crop the two pixels (rows r0, r0+1; col=lane) of one box. Self-contained so
// its many temporaries die before the conv loop (keeps hot-loop regs low).
__device__ __forceinline__ void crop_box(const float* __restrict__ imc,
                                         const float* __restrict__ box,
                                         int lane, int r0,
                                         float& v0, float& v1) {
    float bx = box[0], by = box[1], bw = box[2], bh = box[3];
    float x0 = floorf(bx), y0 = floorf(by);
    float w  = floorf(bx + bw) - x0;
    float h  = floorf(by + bh) - y0;
    int xlo, xhi, ylo0, yhi0, ylo1, yhi1;
    float wx, wy0, wy1;
    axis_coord(x0, w, IMW, lane, xlo, xhi, wx);
    axis_coord(y0, h, IMH, r0,   ylo0, yhi0, wy0);
    axis_coord(y0, h, IMH, r0+1, ylo1, yhi1, wy1);
    {
        int blo = ylo0*IMW, bhi = yhi0*IMW;
        float tl = __ldg(imc + blo + xlo);
        float tr = __ldg(imc + blo + xhi);
        float bl = __ldg(imc + bhi + xlo);
        float br = __ldg(imc + bhi + xhi);
        float top = tl*(1.0f-wx) + tr*wx;
        float bot = bl*(1.0f-wx) + br*wx;
        v0 = top*(1.0f-wy0) + bot*wy0;
    }
    {
        int blo = ylo1*IMW, bhi = yhi1*IMW;
        float tl = __ldg(imc + blo + xlo);
        float tr = __ldg(imc + blo + xhi);
        float bl = __ldg(imc + bhi + xlo);
        float br = __ldg(imc + bhi + xhi);
        float top = tl*(1.0f-wx) + tr*wx;
        float bot = bl*(1.0f-wx) + br*wx;
        v1 = top*(1.0f-wy1) + bot*wy1;
    }
}

// Padded H-field buffer: rows -5..36 (42 rows), index = (realrow+5)*32+lane.
// Pad rows are zero and never rewritten -> V-pass needs no row guards.
#define HROWS 42

__global__ void __launch_bounds__(512, 4)
fused_kernel(const float* __restrict__ gt,
             const float* __restrict__ pr,
             const float* __restrict__ imgs,
             float* __restrict__ out) {
    const unsigned FULL = 0xffffffffu;
    int t = threadIdx.x;
    int lane = t & 31;
    int warp = t >> 5;          // 0..15
    int r0 = warp * 2;          // warp owns rows r0, r0+1; lane owns col=lane
    int idx = blockIdx.x;
    int c  = idx % 3;
    int pi = idx / 3;
    int b  = pi >> 6;
    int p  = pi & 63;

    __shared__ int    s_list[GG];
    __shared__ int    s_nm;
    __shared__ float4 Hb[2][HROWS*SZ];   // 4 fields packed, double-buffered, 43 KB
    __shared__ float  sred[16];
    __shared__ bool   s_last;

    if (t == 0) s_nm = 0;
    // zero the pad rows (rows -5..-1 and 32..36) of both buffers, once
    if (t < 320) {
        int prow = t >> 5;                       // 0..9
        int row  = (prow < 5) ? prow : prow + 32;
        int k = row * SZ + (t & 31);
        float4 z = make_float4(0.0f, 0.0f, 0.0f, 0.0f);
        Hb[0][k] = z; Hb[1][k] = z;
    }
    __syncthreads();

    // IoU mask of this pred against all 16 gts
    const float* pb = pr + (size_t)(b*PP + p)*4;
    float px_ = pb[0], py_ = pb[1], pw_ = pb[2], ph_ = pb[3];
    if (t < GG) {
        const float* gb = gt + (size_t)(b*GG + t)*4;
        float gx = gb[0], gy = gb[1], gw_ = gb[2], gh_ = gb[3];
        float tlx = fmaxf(gx - gw_*0.5f, px_ - pw_*0.5f);
        float tly = fmaxf(gy - gh_*0.5f, py_ - ph_*0.5f);
        float brx = fminf(gx + gw_*0.5f, px_ + pw_*0.5f);
        float bry = fminf(gy + gh_*0.5f, py_ + ph_*0.5f);
        float en  = ((tlx < brx) && (tly < bry)) ? 1.0f : 0.0f;
        float ai  = (brx - tlx) * (bry - tly) * en;
        float iou = ai / (gw_*gh_ + pw_*ph_ - ai + 1e-16f);
        if ((iou > 0.3f) && (pw_ > 2.0f) && (ph_ > 2.0f)) {
            int i = atomicAdd(&s_nm, 1);
            s_list[i] = t;
        }
    }
    __syncthreads();
    int nm = s_nm;

    if (nm > 0) {
        const float* imc = imgs + ((size_t)b * 3 + c) * IMH * IMW;
        const float C1 = 6.5025f;    // (0.01*255)^2
        const float C2 = 58.5225f;   // (0.03*255)^2
        float accf = 0.0f;

        // pred crop: channel fixed per block -> hoist out of gt loop
        float x0v, x1v;
        crop_box(imc, pb, lane, r0, x0v, x1v);

        for (int m = 0; m < nm; m++) {
            int buf = m & 1;
            float y0v, y1v;
            crop_box(imc, gt + (size_t)(b*GG + s_list[m])*4, lane, r0, y0v, y1v);

            // horizontal pass via warp shuffles, zero-pad SAME, 4 fields
            #pragma unroll
            for (int rr = 0; rr < 2; rr++) {
                float xv = rr ? x1v : x0v;
                float yv = rr ? y1v : y0v;
                float h0=0.f,h1=0.f,h2=0.f,h3=0.f;
                #pragma unroll
                for (int d = -5; d <= 5; d++) {
                    float xs = __shfl_sync(FULL, xv, lane + d);
                    float ys = __shfl_sync(FULL, yv, lane + d);
                    if ((unsigned)(lane + d) < 32u) {
                        const float wv = GW[d < 0 ? -d : d];   // immediate
                        h0 = fmaf(wv, xs, h0);
                        h1 = fmaf(wv, ys, h1);
                        h2 = fmaf(wv, fmaf(xs, xs, ys*ys), h2);
                        h3 = fmaf(wv, xs*ys, h3);
                    }
                }
                int k = (r0 + rr + 5) * SZ + lane;   // padded row index
                Hb[buf][k] = make_float4(h0, h1, h2, h3);
            }
            __syncthreads();   // single barrier per gt (double buffer)

            // vertical pass over padded rows r0..r0+11, no guards (pads are zero)
            float v00=0.f,v01=0.f,v02=0.f,v03=0.f;
            float v10=0.f,v11=0.f,v12=0.f,v13=0.f;
            #pragma unroll
            for (int dd = 0; dd <= 11; dd++) {
                int k = (r0 + dd) * SZ + lane;
                float4 f = Hb[buf][k];
                if (dd <= 10) {                    // tap for output row r0
                    const float wv = GW[dd < 5 ? 5 - dd : dd - 5];
                    v00 = fmaf(wv, f.x, v00);
                    v01 = fmaf(wv, f.y, v01);
                    v02 = fmaf(wv, f.z, v02);
                    v03 = fmaf(wv, f.w, v03);
                }
                if (dd >= 1) {                     // tap for output row r0+1
                    const float wv = GW[dd < 6 ? 6 - dd : dd - 6];
                    v10 = fmaf(wv, f.x, v10);
                    v11 = fmaf(wv, f.y, v11);
                    v12 = fmaf(wv, f.z, v12);
                    v13 = fmaf(wv, f.w, v13);
                }
            }

            // SSIM + L1 for the two pixels
            {
                float mu1 = v00, mu2 = v01;
                float mu1sq = mu1*mu1, mu2sq = mu2*mu2, mu12 = mu1*mu2;
                float sS  = v02 - mu1sq - mu2sq;   // s1 + s2
                float s12 = v03 - mu12;
                float ssim = ((2.0f*mu12 + C1) * (2.0f*s12 + C2))
                           / ((mu1sq + mu2sq + C1) * (sS + C2));
                accf += fabsf(x0v*(1.0f/255.0f) - y0v*(1.0f/255.0f)) + (1.0f - ssim);
            }
            {
                float mu1 = v10, mu2 = v11;
                float mu1sq = mu1*mu1, mu2sq = mu2*mu2, mu12 = mu1*mu2;
                float sS  = v12 - mu1sq - mu2sq;
                float s12 = v13 - mu12;
                float ssim = ((2.0f*mu12 + C1) * (2.0f*s12 + C2))
                           / ((mu1sq + mu2sq + C1) * (sS + C2));
                accf += fabsf(x1v*(1.0f/255.0f) - y1v*(1.0f/255.0f)) + (1.0f - ssim);
            }
            // no trailing barrier: next gt writes the other buffer
        }

        // block reduction (16 warps)
        #pragma unroll
        for (int o = 16; o > 0; o >>= 1) accf += __shfl_down_sync(FULL, accf, o);
        if (lane == 0) sred[warp] = accf;
        __syncthreads();
        if (t < 16) {
            float v = sred[t];
            #pragma unroll
            for (int o = 8; o > 0; o >>= 1) v += __shfl_down_sync(0xffffu, v, o);
            if (t == 0) {
                atomicAdd(&d_total, (double)v);
                if (c == 0) atomicAdd(&d_cnt, (double)nm);
            }
        }
    }

    // completion counter: last block finalizes and resets accumulators
    __threadfence();
    if (t == 0) {
        unsigned prev = atomicAdd(&d_done, 1u);
        s_last = (prev == (unsigned)(NBLOCKS - 1));
    }
    __syncthreads();
    if (s_last && t == 0) {
        double cnt = d_cnt * (double)(3*SZ*SZ);
        out[0] = (cnt > 0.0) ? (float)(d_total / fmax(cnt, 1.0)) : 0.0f;
        d_total = 0.0;
        d_cnt   = 0.0;
        d_done  = 0u;
    }
}

extern "C" void kernel_launch(void* const* d_in, const int* in_sizes, int n_in,
                              void* d_out, int out_size) {
    const float* gt   = (const float*)d_in[0];
    const float* pr   = (const float*)d_in[1];
    const float* imgs = (const float*)d_in[2];
    float* out = (float*)d_out;

    fused_kernel<<<NBLOCKS, 512>>>(gt, pr, imgs, out);
}

// round 9
// speedup vs baseline: 1.8195x; 1.0146x over previous
#include <cuda_runtime.h>
#include <math.h>

#define BB 8
#define GG 16
#define PP 64
#define IMH 640
#define IMW 640
#define SZ 32
#define NITEMS (BB*PP*3)
#define NPBLOCKS (148*4)

// Gaussian window weights for WIN=11, sigma=1.5 (exp(-d^2/4.5), normalized),
// accurate to ~1e-8 vs the float64 reference; constexpr -> FFMA immediates.
__device__ constexpr float GW[6] = {
    0.26601172f,   // |d|=0
    0.21300554f,   // |d|=1
    0.10936070f,   // |d|=2
    0.03600077f,   // |d|=3
    0.00759876f,   // |d|=4
    0.00102838f    // |d|=5
};

__device__ double d_total = 0.0;
__device__ double d_cnt   = 0.0;
__device__ unsigned int d_done = 0;
__device__ unsigned int d_work = 0;

// Per-axis bilinear sampling coords, same arithmetic order as reference
__device__ __forceinline__ void axis_coord(float origin, float len, int maxdim, int i,
                                           int& lo, int& hi, float& wq) {
    float lm = fmaxf(len - 1.0f, 0.0f);
    float s  = fminf(fmaxf(((float)i + 0.5f) * (len / (float)SZ) - 0.5f, 0.0f), lm);
    float sf = floorf(s);
    wq = s - sf;
    float vlo = sf + origin;
    float vhi = fminf(sf + 1.0f, lm) + origin;
    lo = (int)fminf(fmaxf(vlo, 0.0f), (float)(maxdim - 1));
    hi = (int)fminf(fmaxf(vhi, 0.0f), (float)(maxdim - 1));
}

// Crop the two pixels (rows r0, r0+1; col=lane) of one box. Self-contained so
// its temporaries die before the conv loop (keeps hot-loop regs low).
__device__ __forceinline__ void crop_box(const float* __restrict__ imc,
                                         const float* __restrict__ box,
                                         int lane, int r0,
                                         float& v0, float& v1) {
    float bx = box[0], by = box[1], bw = box[2], bh = box[3];
    float x0 = floorf(bx), y0 = floorf(by);
    float w  = floorf(bx + bw) - x0;
    float h  = floorf(by + bh) - y0;
    int xlo, xhi, ylo0, yhi0, ylo1, yhi1;
    float wx, wy0, wy1;
    axis_coord(x0, w, IMW, lane, xlo, xhi, wx);
    axis_coord(y0, h, IMH, r0,   ylo0, yhi0, wy0);
    axis_coord(y0, h, IMH, r0+1, ylo1, yhi1, wy1);
    {
        int blo = ylo0*IMW, bhi = yhi0*IMW;
        float tl = __ldg(imc + blo + xlo);
        float tr = __ldg(imc + blo + xhi);
        float bl = __ldg(imc + bhi + xlo);
        float br = __ldg(imc + bhi + xhi);
        float top = tl*(1.0f-wx) + tr*wx;
        float bot = bl*(1.0f-wx) + br*wx;
        v0 = top*(1.0f-wy0) + bot*wy0;
    }
    {
        int blo = ylo1*IMW, bhi = yhi1*IMW;
        float tl = __ldg(imc + blo + xlo);
        float tr = __ldg(imc + blo + xhi);
        float bl = __ldg(imc + bhi + xlo);
        float br = __ldg(imc + bhi + xhi);
        float top = tl*(1.0f-wx) + tr*wx;
        float bot = bl*(1.0f-wx) + br*wx;
        v1 = top*(1.0f-wy1) + bot*wy1;
    }
}

// Padded H-field buffer: rows -5..36 (42 rows), index = (realrow+5)*32+lane.
// Pad rows are zero and never rewritten -> V-pass needs no row guards.
#define HROWS 42

__global__ void __launch_bounds__(512, 4)
fused_kernel(const float* __restrict__ gt,
             const float* __restrict__ pr,
             const float* __restrict__ imgs,
             float* __restrict__ out) {
    const unsigned FULL = 0xffffffffu;
    int t = threadIdx.x;
    int lane = t & 31;
    int warp = t >> 5;          // 0..15
    int r0 = warp * 2;          // warp owns rows r0, r0+1; lane owns col=lane

    __shared__ int    s_item;
    __shared__ int    s_list[GG];
    __shared__ int    s_nm;
    __shared__ float4 Hb[2][HROWS*SZ];   // 4 fields packed, double-buffered, 43 KB
    __shared__ float  sred[16];
    __shared__ bool   s_last;

    // zero the pad rows (rows -5..-1 and 32..36) of both buffers, once per block
    if (t < 320) {
        int prow = t >> 5;                       // 0..9
        int row  = (prow < 5) ? prow : prow + 32;
        int k = row * SZ + (t & 31);
        float4 z = make_float4(0.0f, 0.0f, 0.0f, 0.0f);
        Hb[0][k] = z; Hb[1][k] = z;
    }

    const float C1 = 6.5025f;    // (0.01*255)^2
    const float C2 = 58.5225f;   // (0.03*255)^2
    float accf   = 0.0f;   // per-thread loss accumulator, carried across items
    int   cntloc = 0;      // masked-pair count (t==0 meaningful), c==0 items only

    // ---- persistent work loop: items are (pred, channel) ----
    while (true) {
        if (t == 0) {
            s_item = (int)atomicAdd(&d_work, 1u);
            s_nm = 0;
        }
        __syncthreads();
        int item = s_item;
        if (item >= NITEMS) break;

        int c  = item % 3;
        int pi = item / 3;
        int b  = pi >> 6;
        int p  = pi & 63;

        // IoU mask of this pred against all 16 gts
        const float* pb = pr + (size_t)(b*PP + p)*4;
        float pw_ = pb[2], ph_ = pb[3];
        if (t < GG) {
            float px_ = pb[0], py_ = pb[1];
            const float* gb = gt + (size_t)(b*GG + t)*4;
            float gx = gb[0], gy = gb[1], gw_ = gb[2], gh_ = gb[3];
            float tlx = fmaxf(gx - gw_*0.5f, px_ - pw_*0.5f);
            float tly = fmaxf(gy - gh_*0.5f, py_ - ph_*0.5f);
            float brx = fminf(gx + gw_*0.5f, px_ + pw_*0.5f);
            float bry = fminf(gy + gh_*0.5f, py_ + ph_*0.5f);
            float en  = ((tlx < brx) && (tly < bry)) ? 1.0f : 0.0f;
            float ai  = (brx - tlx) * (bry - tly) * en;
            float iou = ai / (gw_*gh_ + pw_*ph_ - ai + 1e-16f);
            if ((iou > 0.3f) && (pw_ > 2.0f) && (ph_ > 2.0f)) {
                int i = atomicAdd(&s_nm, 1);
                s_list[i] = t;
            }
        }
        __syncthreads();
        int nm = s_nm;
        if (nm == 0) continue;

        if (t == 0 && c == 0) cntloc += nm;

        const float* imc = imgs + ((size_t)b * 3 + c) * IMH * IMW;

        // pred crop: channel fixed per item -> hoist out of gt loop
        float x0v, x1v;
        crop_box(imc, pb, lane, r0, x0v, x1v);

        for (int m = 0; m < nm; m++) {
            int buf = m & 1;
            float y0v, y1v;
            crop_box(imc, gt + (size_t)(b*GG + s_list[m])*4, lane, r0, y0v, y1v);

            // horizontal pass via warp shuffles, zero-pad SAME, 4 fields
            #pragma unroll
            for (int rr = 0; rr < 2; rr++) {
                float xv = rr ? x1v : x0v;
                float yv = rr ? y1v : y0v;
                float h0=0.f,h1=0.f,h2=0.f,h3=0.f;
                #pragma unroll
                for (int d = -5; d <= 5; d++) {
                    float xs = __shfl_sync(FULL, xv, lane + d);
                    float ys = __shfl_sync(FULL, yv, lane + d);
                    if ((unsigned)(lane + d) < 32u) {
                        const float wv = GW[d < 0 ? -d : d];   // immediate
                        h0 = fmaf(wv, xs, h0);
                        h1 = fmaf(wv, ys, h1);
                        h2 = fmaf(wv, fmaf(xs, xs, ys*ys), h2);
                        h3 = fmaf(wv, xs*ys, h3);
                    }
                }
                int k = (r0 + rr + 5) * SZ + lane;   // padded row index
                Hb[buf][k] = make_float4(h0, h1, h2, h3);
            }
            __syncthreads();   // single barrier per gt (double buffer)

            // vertical pass over padded rows r0..r0+11, no guards (pads are zero)
            float v00=0.f,v01=0.f,v02=0.f,v03=0.f;
            float v10=0.f,v11=0.f,v12=0.f,v13=0.f;
            #pragma unroll
            for (int dd = 0; dd <= 11; dd++) {
                int k = (r0 + dd) * SZ + lane;
                float4 f = Hb[buf][k];
                if (dd <= 10) {                    // tap for output row r0
                    const float wv = GW[dd < 5 ? 5 - dd : dd - 5];
                    v00 = fmaf(wv, f.x, v00);
                    v01 = fmaf(wv, f.y, v01);
                    v02 = fmaf(wv, f.z, v02);
                    v03 = fmaf(wv, f.w, v03);
                }
                if (dd >= 1) {                     // tap for output row r0+1
                    const float wv = GW[dd < 6 ? 6 - dd : dd - 6];
                    v10 = fmaf(wv, f.x, v10);
                    v11 = fmaf(wv, f.y, v11);
                    v12 = fmaf(wv, f.z, v12);
                    v13 = fmaf(wv, f.w, v13);
                }
            }

            // SSIM + L1 for the two pixels
            {
                float mu1 = v00, mu2 = v01;
                float mu1sq = mu1*mu1, mu2sq = mu2*mu2, mu12 = mu1*mu2;
                float sS  = v02 - mu1sq - mu2sq;   // s1 + s2
                float s12 = v03 - mu12;
                float ssim = ((2.0f*mu12 + C1) * (2.0f*s12 + C2))
                           / ((mu1sq + mu2sq + C1) * (sS + C2));
                accf += fabsf(x0v*(1.0f/255.0f) - y0v*(1.0f/255.0f)) + (1.0f - ssim);
            }
            {
                float mu1 = v10, mu2 = v11;
                float mu1sq = mu1*mu1, mu2sq = mu2*mu2, mu12 = mu1*mu2;
                float sS  = v12 - mu1sq - mu2sq;
                float s12 = v13 - mu12;
                float ssim = ((2.0f*mu12 + C1) * (2.0f*s12 + C2))
                           / ((mu1sq + mu2sq + C1) * (sS + C2));
                accf += fabsf(x1v*(1.0f/255.0f) - y1v*(1.0f/255.0f)) + (1.0f - ssim);
            }
            // no trailing barrier: next gt writes the other buffer; item
            // boundary is covered by the two barriers in the pop/IoU prologue
        }
    }

    // ---- one block reduction at the end (16 warps) ----
    #pragma unroll
    for (int o = 16; o > 0; o >>= 1) accf += __shfl_down_sync(FULL, accf, o);
    if (lane == 0) sred[warp] = accf;
    __syncthreads();
    if (t < 16) {
        float v = sred[t];
        #pragma unroll
        for (int o = 8; o > 0; o >>= 1) v += __shfl_down_sync(0xffffu, v, o);
        if (t == 0) {
            if (v != 0.0f)  atomicAdd(&d_total, (double)v);
            if (cntloc > 0) atomicAdd(&d_cnt, (double)cntloc);
        }
    }

    // completion counter: last block finalizes and resets all globals
    __threadfence();
    if (t == 0) {
        unsigned prev = atomicAdd(&d_done, 1u);
        s_last = (prev == (unsigned)(NPBLOCKS - 1));
    }
    __syncthreads();
    if (s_last && t == 0) {
        double cnt = d_cnt * (double)(3*SZ*SZ);
        out[0] = (cnt > 0.0) ? (float)(d_total / fmax(cnt, 1.0)) : 0.0f;
        d_total = 0.0;
        d_cnt   = 0.0;
        d_done  = 0u;
        d_work  = 0u;
    }
}

extern "C" void kernel_launch(void* const* d_in, const int* in_sizes, int n_in,
                              void* d_out, int out_size) {
    const float* gt   = (const float*)d_in[0];
    const float* pr   = (const float*)d_in[1];
    const float* imgs = (const float*)d_in[2];
    float* out = (float*)d_out;

    fused_kernel<<<NPBLOCKS, 512>>>(gt, pr, imgs, out);
}

// round 10
// speedup vs baseline: 1.9162x; 1.0531x over previous
#include <cuda_runtime.h>
#include <math.h>

#define BB 8
#define GG 16
#define PP 64
#define IMH 640
#define IMW 640
#define SZ 32
#define NITEMS (BB*PP*3)
#define NPBLOCKS (148*4)

// Gaussian window weights for WIN=11, sigma=1.5 (exp(-d^2/4.5), normalized),
// accurate to ~1e-8 vs the float64 reference; constexpr -> FFMA immediates.
__device__ constexpr float GW[6] = {
    0.26601172f,   // |d|=0
    0.21300554f,   // |d|=1
    0.10936070f,   // |d|=2
    0.03600077f,   // |d|=3
    0.00759876f,   // |d|=4
    0.00102838f    // |d|=5
};

__device__ double d_total = 0.0;
__device__ double d_cnt   = 0.0;
__device__ unsigned int d_done = 0;
__device__ unsigned int d_work = 0;

// Per-axis bilinear sampling coords, same arithmetic order as reference
__device__ __forceinline__ void axis_coord(float origin, float len, int maxdim, int i,
                                           int& lo, int& hi, float& wq) {
    float lm = fmaxf(len - 1.0f, 0.0f);
    float s  = fminf(fmaxf(((float)i + 0.5f) * (len / (float)SZ) - 0.5f, 0.0f), lm);
    float sf = floorf(s);
    wq = s - sf;
    float vlo = sf + origin;
    float vhi = fminf(sf + 1.0f, lm) + origin;
    lo = (int)fminf(fmaxf(vlo, 0.0f), (float)(maxdim - 1));
    hi = (int)fminf(fmaxf(vhi, 0.0f), (float)(maxdim - 1));
}

// Crop the two pixels (rows r0, r0+1; col=lane) of one box. Self-contained so
// its temporaries die before the conv loop (keeps hot-loop regs low).
__device__ __forceinline__ void crop_box(const float* __restrict__ imc,
                                         const float* __restrict__ box,
                                         int lane, int r0,
                                         float& v0, float& v1) {
    float bx = box[0], by = box[1], bw = box[2], bh = box[3];
    float x0 = floorf(bx), y0 = floorf(by);
    float w  = floorf(bx + bw) - x0;
    float h  = floorf(by + bh) - y0;
    int xlo, xhi, ylo0, yhi0, ylo1, yhi1;
    float wx, wy0, wy1;
    axis_coord(x0, w, IMW, lane, xlo, xhi, wx);
    axis_coord(y0, h, IMH, r0,   ylo0, yhi0, wy0);
    axis_coord(y0, h, IMH, r0+1, ylo1, yhi1, wy1);
    {
        int blo = ylo0*IMW, bhi = yhi0*IMW;
        float tl = __ldg(imc + blo + xlo);
        float tr = __ldg(imc + blo + xhi);
        float bl = __ldg(imc + bhi + xlo);
        float br = __ldg(imc + bhi + xhi);
        float top = tl*(1.0f-wx) + tr*wx;
        float bot = bl*(1.0f-wx) + br*wx;
        v0 = top*(1.0f-wy0) + bot*wy0;
    }
    {
        int blo = ylo1*IMW, bhi = yhi1*IMW;
        float tl = __ldg(imc + blo + xlo);
        float tr = __ldg(imc + blo + xhi);
        float bl = __ldg(imc + bhi + xlo);
        float br = __ldg(imc + bhi + xhi);
        float top = tl*(1.0f-wx) + tr*wx;
        float bot = bl*(1.0f-wx) + br*wx;
        v1 = top*(1.0f-wy1) + bot*wy1;
    }
}

// Padded H-field buffer: rows -5..36 (42 rows), index = (realrow+5)*32+lane.
// Pad rows are zero and never rewritten -> V-pass needs no row guards.
#define HROWS 42

__global__ void __launch_bounds__(512, 4)
fused_kernel(const float* __restrict__ gt,
             const float* __restrict__ pr,
             const float* __restrict__ imgs,
             float* __restrict__ out) {
    const unsigned FULL = 0xffffffffu;
    int t = threadIdx.x;
    int lane = t & 31;
    int warp = t >> 5;          // 0..15
    int r0 = warp * 2;          // warp owns rows r0, r0+1; lane owns col=lane

    __shared__ int      s_item;
    __shared__ unsigned s_mask;
    __shared__ float4   Hb[2][HROWS*SZ];   // 4 fields packed, double-buffered, 43 KB
    __shared__ float    sred[16];
    __shared__ bool     s_last;

    // zero the pad rows (rows -5..-1 and 32..36) of both buffers, once per block
    if (t < 320) {
        int prow = t >> 5;                       // 0..9
        int row  = (prow < 5) ? prow : prow + 32;
        int k = row * SZ + (t & 31);
        float4 z = make_float4(0.0f, 0.0f, 0.0f, 0.0f);
        Hb[0][k] = z; Hb[1][k] = z;
    }

    const float C1 = 6.5025f;    // (0.01*255)^2
    const float C2 = 58.5225f;   // (0.03*255)^2
    float accf   = 0.0f;   // per-thread loss accumulator, carried across items
    int   cntloc = 0;      // masked-pair count (t==0 meaningful), c==0 items only

    // ---- persistent work loop: items are (pred, channel) ----
    while (true) {
        // warp 0: pop next item and compute the 16-gt IoU mask via ballot
        if (warp == 0) {
            int item;
            if (lane == 0) item = (int)atomicAdd(&d_work, 1u);
            item = __shfl_sync(FULL, item, 0);
            bool pass = false;
            if (item < NITEMS && lane < GG) {
                int pi = item / 3;
                int b  = pi >> 6;
                int p  = pi & 63;
                const float* pb2 = pr + (size_t)(b*PP + p)*4;
                float px_ = pb2[0], py_ = pb2[1], pw_ = pb2[2], ph_ = pb2[3];
                const float* gb = gt + (size_t)(b*GG + lane)*4;
                float gx = gb[0], gy = gb[1], gw_ = gb[2], gh_ = gb[3];
                float tlx = fmaxf(gx - gw_*0.5f, px_ - pw_*0.5f);
                float tly = fmaxf(gy - gh_*0.5f, py_ - ph_*0.5f);
                float brx = fminf(gx + gw_*0.5f, px_ + pw_*0.5f);
                float bry = fminf(gy + gh_*0.5f, py_ + ph_*0.5f);
                float en  = ((tlx < brx) && (tly < bry)) ? 1.0f : 0.0f;
                float ai  = (brx - tlx) * (bry - tly) * en;
                float iou = ai / (gw_*gh_ + pw_*ph_ - ai + 1e-16f);
                pass = (iou > 0.3f) && (pw_ > 2.0f) && (ph_ > 2.0f);
            }
            unsigned msk = __ballot_sync(FULL, pass);
            if (lane == 0) { s_item = item; s_mask = msk; }
        }
        __syncthreads();                  // pop + mask visible to all
        int      item = s_item;
        unsigned mask = s_mask;
        if (item >= NITEMS) break;

        int nm = __popc((int)mask);
        if (nm == 0) {
            __syncthreads();              // all read s_item before next overwrite
            continue;
        }
        // for nm>0, the per-gt barrier below provides that separation

        int c  = item % 3;
        int pi = item / 3;
        int b  = pi >> 6;
        int p  = pi & 63;
        if (t == 0 && c == 0) cntloc += nm;

        const float* imc = imgs + ((size_t)b * 3 + c) * IMH * IMW;
        const float* pb  = pr + (size_t)(b*PP + p)*4;

        // pred crop: channel fixed per item -> hoist out of gt loop
        float x0v, x1v;
        crop_box(imc, pb, lane, r0, x0v, x1v);

        for (int m = 0; m < nm; m++) {
            int buf = m & 1;
            int g = __ffs((int)mask) - 1;
            mask &= mask - 1u;
            float y0v, y1v;
            crop_box(imc, gt + (size_t)(b*GG + g)*4, lane, r0, y0v, y1v);

            // horizontal pass via immediate-delta shuffles, zero-pad SAME.
            // center tap needs no shuffle; +/-d via shfl.down/shfl.up.
            #pragma unroll
            for (int rr = 0; rr < 2; rr++) {
                float xv = rr ? x1v : x0v;
                float yv = rr ? y1v : y0v;
                float h0, h1, h2, h3;
                {   // d = 0
                    const float w0 = GW[0];
                    h0 = w0 * xv;
                    h1 = w0 * yv;
                    h2 = w0 * fmaf(xv, xv, yv*yv);
                    h3 = w0 * (xv*yv);
                }
                #pragma unroll
                for (int d = 1; d <= 5; d++) {
                    const float wv = GW[d];
                    float xp = __shfl_down_sync(FULL, xv, d);  // lane+d
                    float yp = __shfl_down_sync(FULL, yv, d);
                    float xm = __shfl_up_sync(FULL, xv, d);    // lane-d
                    float ym = __shfl_up_sync(FULL, yv, d);
                    if (lane + d < 32) {
                        h0 = fmaf(wv, xp, h0);
                        h1 = fmaf(wv, yp, h1);
                        h2 = fmaf(wv, fmaf(xp, xp, yp*yp), h2);
                        h3 = fmaf(wv, xp*yp, h3);
                    }
                    if (lane >= d) {
                        h0 = fmaf(wv, xm, h0);
                        h1 = fmaf(wv, ym, h1);
                        h2 = fmaf(wv, fmaf(xm, xm, ym*ym), h2);
                        h3 = fmaf(wv, xm*ym, h3);
                    }
                }
                int k = (r0 + rr + 5) * SZ + lane;   // padded row index
                Hb[buf][k] = make_float4(h0, h1, h2, h3);
            }
            __syncthreads();   // single barrier per gt (double buffer)

            // vertical pass over padded rows r0..r0+11, no guards (pads are zero)
            float v00=0.f,v01=0.f,v02=0.f,v03=0.f;
            float v10=0.f,v11=0.f,v12=0.f,v13=0.f;
            #pragma unroll
            for (int dd = 0; dd <= 11; dd++) {
                int k = (r0 + dd) * SZ + lane;
                float4 f = Hb[buf][k];
                if (dd <= 10) {                    // tap for output row r0
                    const float wv = GW[dd < 5 ? 5 - dd : dd - 5];
                    v00 = fmaf(wv, f.x, v00);
                    v01 = fmaf(wv, f.y, v01);
                    v02 = fmaf(wv, f.z, v02);
                    v03 = fmaf(wv, f.w, v03);
                }
                if (dd >= 1) {                     // tap for output row r0+1
                    const float wv = GW[dd < 6 ? 6 - dd : dd - 6];
                    v10 = fmaf(wv, f.x, v10);
                    v11 = fmaf(wv, f.y, v11);
                    v12 = fmaf(wv, f.z, v12);
                    v13 = fmaf(wv, f.w, v13);
                }
            }

            // SSIM + L1 for the two pixels (fast division: ~2ulp, tol 1e-3)
            {
                float mu1 = v00, mu2 = v01;
                float mu1sq = mu1*mu1, mu2sq = mu2*mu2, mu12 = mu1*mu2;
                float sS  = v02 - mu1sq - mu2sq;   // s1 + s2
                float s12 = v03 - mu12;
                float ssim = __fdividef((2.0f*mu12 + C1) * (2.0f*s12 + C2),
                                        (mu1sq + mu2sq + C1) * (sS + C2));
                accf += fabsf(x0v*(1.0f/255.0f) - y0v*(1.0f/255.0f)) + (1.0f - ssim);
            }
            {
                float mu1 = v10, mu2 = v11;
                float mu1sq = mu1*mu1, mu2sq = mu2*mu2, mu12 = mu1*mu2;
                float sS  = v12 - mu1sq - mu2sq;
                float s12 = v13 - mu12;
                float ssim = __fdividef((2.0f*mu12 + C1) * (2.0f*s12 + C2),
                                        (mu1sq + mu2sq + C1) * (sS + C2));
                accf += fabsf(x1v*(1.0f/255.0f) - y1v*(1.0f/255.0f)) + (1.0f - ssim);
            }
            // no trailing barrier: next gt writes the other buffer
        }
    }

    // ---- one block reduction at the end (16 warps) ----
    #pragma unroll
    for (int o = 16; o > 0; o >>= 1) accf += __shfl_down_sync(FULL, accf, o);
    if (lane == 0) sred[warp] = accf;
    __syncthreads();
    if (t < 16) {
        float v = sred[t];
        #pragma unroll
        for (int o = 8; o > 0; o >>= 1) v += __shfl_down_sync(0xffffu, v, o);
        if (t == 0) {
            if (v != 0.0f)  atomicAdd(&d_total, (double)v);
            if (cntloc > 0) atomicAdd(&d_cnt, (double)cntloc);
        }
    }

    // completion counter: last block finalizes and resets all globals
    __threadfence();
    if (t == 0) {
        unsigned prev = atomicAdd(&d_done, 1u);
        s_last = (prev == (unsigned)(NPBLOCKS - 1));
    }
    __syncthreads();
    if (s_last && t == 0) {
        double cnt = d_cnt * (double)(3*SZ*SZ);
        out[0] = (cnt > 0.0) ? (float)(d_total / fmax(cnt, 1.0)) : 0.0f;
        d_total = 0.0;
        d_cnt   = 0.0;
        d_done  = 0u;
        d_work  = 0u;
    }
}

extern "C" void kernel_launch(void* const* d_in, const int* in_sizes, int n_in,
                              void* d_out, int out_size) {
    const float* gt   = (const float*)d_in[0];
    const float* pr   = (const float*)d_in[1];
    const float* imgs = (const float*)d_in[2];
    float* out = (float*)d_out;

    fused_kernel<<<NPBLOCKS, 512>>>(gt, pr, imgs, out);
}